// round 3
// baseline (speedup 1.0000x reference)
#include <cuda_runtime.h>
#include <cuda_bf16.h>
#include <math.h>

// Problem constants
#define B_  8
#define C_  256
#define T_  8
#define H_  56
#define W_  56
#define HW_ (H_*W_)
#define CR_ 64

// Scratch (device globals: sanctioned workaround for no-alloc rule)
__device__ float  g_pool[B_*C_*T_];           // [b][c][t]
__device__ float  g_walpha[B_*C_*T_];         // [b][c][t]
__device__ float  g_balpha[B_*C_*T_];         // [b][c][t]
__device__ float  g_conv[(size_t)B_*C_*T_*HW_]; // conv output, pre-BN
__device__ double g_stats[C_][4];             // sum, sumsq, sum_ap, sumsq_ap

// ---------------------------------------------------------------------------
// Kernel 1: spatial mean pool  feat[b,c,t,:,:] -> g_pool[b,c,t]
// ---------------------------------------------------------------------------
__global__ void pool_kernel(const float* __restrict__ feat) {
    int bct = blockIdx.x;                 // (b*256+c)*8+t
    const float* p = feat + (size_t)bct * HW_;
    float s = 0.f;
    for (int i = threadIdx.x; i < HW_; i += blockDim.x) s += p[i];
    // reduce
    for (int o = 16; o; o >>= 1) s += __shfl_down_sync(0xffffffffu, s, o);
    __shared__ float sb[8];
    int lane = threadIdx.x & 31, w = threadIdx.x >> 5;
    if (lane == 0) sb[w] = s;
    __syncthreads();
    if (threadIdx.x == 0) {
        float t = 0.f;
        int nw = blockDim.x >> 5;
        for (int i = 0; i < nw; i++) t += sb[i];
        g_pool[bct] = t * (1.f / HW_);
    }
}

// ---------------------------------------------------------------------------
// Kernel 2: routing network, one block per batch b (256 threads)
// produces g_walpha, g_balpha
// ---------------------------------------------------------------------------
__device__ __forceinline__ float qgelu(float x) {
    return x / (1.f + __expf(-1.702f * x));
}

__global__ void routing_kernel(
    const float* __restrict__ a_w, const float* __restrict__ a_b,
    const float* __restrict__ norm_w, const float* __restrict__ norm_b,
    const float* __restrict__ normt_w, const float* __restrict__ normt_b,
    const float* __restrict__ qkv_w, const float* __restrict__ qkv_b,
    const float* __restrict__ ao_w, const float* __restrict__ ao_b,
    const float* __restrict__ b_w, const float* __restrict__ bb_w)
{
    int b = blockIdx.x;
    int tid = threadIdx.x;

    __shared__ float s_pool[C_][T_];
    __shared__ float s_x1[CR_][T_];
    __shared__ float s_x2[CR_][T_];
    __shared__ float s_xn[CR_][T_];
    __shared__ float s_qkv[3*CR_][T_];
    __shared__ float s_att[T_][T_];
    __shared__ float s_o[CR_][T_];
    __shared__ float s_mu[T_], s_rstd[T_];

    for (int i = tid; i < C_*T_; i += 256) s_pool[i >> 3][i & 7] = g_pool[b*C_*T_ + i];
    __syncthreads();

    // conv 'a' : [64][8]
    for (int idx = tid; idx < CR_*T_; idx += 256) {
        int r = idx >> 3, t = idx & 7;
        float acc = a_b[r];
        const float* wbase = a_w + (size_t)r * C_ * 3;
        for (int c = 0; c < C_; c++) {
            float p0 = (t > 0) ? s_pool[c][t-1] : 0.f;
            float p1 = s_pool[c][t];
            float p2 = (t < 7) ? s_pool[c][t+1] : 0.f;
            const float* w = wbase + c*3;
            acc += w[0]*p0 + w[1]*p1 + w[2]*p2;
        }
        s_x1[r][t] = acc;
    }
    __syncthreads();

    // LN over channel (64) per t  + qGELU  -> s_x2
    if (tid < T_) {
        int t = tid;
        float mu = 0.f;
        for (int r = 0; r < CR_; r++) mu += s_x1[r][t];
        mu *= (1.f / CR_);
        float v = 0.f;
        for (int r = 0; r < CR_; r++) { float d = s_x1[r][t] - mu; v += d*d; }
        v *= (1.f / CR_);
        s_mu[t] = mu; s_rstd[t] = rsqrtf(v + 1e-6f);
    }
    __syncthreads();
    for (int idx = tid; idx < CR_*T_; idx += 256) {
        int r = idx >> 3, t = idx & 7;
        float xln = (s_x1[r][t] - s_mu[t]) * s_rstd[t] * norm_w[r] + norm_b[r];
        s_x2[r][t] = qgelu(xln);
    }
    __syncthreads();

    // second LN -> s_xn
    if (tid < T_) {
        int t = tid;
        float mu = 0.f;
        for (int r = 0; r < CR_; r++) mu += s_x2[r][t];
        mu *= (1.f / CR_);
        float v = 0.f;
        for (int r = 0; r < CR_; r++) { float d = s_x2[r][t] - mu; v += d*d; }
        v *= (1.f / CR_);
        s_mu[t] = mu; s_rstd[t] = rsqrtf(v + 1e-6f);
    }
    __syncthreads();
    for (int idx = tid; idx < CR_*T_; idx += 256) {
        int r = idx >> 3, t = idx & 7;
        s_xn[r][t] = (s_x2[r][t] - s_mu[t]) * s_rstd[t] * normt_w[r] + normt_b[r];
    }
    __syncthreads();

    // qkv: [192][8]
    for (int idx = tid; idx < 3*CR_*T_; idx += 256) {
        int o = idx >> 3, t = idx & 7;
        float acc = qkv_b[o];
        const float* w = qkv_w + (size_t)o * CR_;
        for (int c = 0; c < CR_; c++) acc += w[c] * s_xn[c][t];
        s_qkv[o][t] = acc;
    }
    __syncthreads();

    // attention scores (1 head, hd=64): s[i][j] = 0.125 * sum_d q[d][i]*k[d][j]
    if (tid < T_*T_) {
        int i = tid >> 3, j = tid & 7;
        float a = 0.f;
        for (int d = 0; d < CR_; d++) a += s_qkv[d][i] * s_qkv[CR_ + d][j];
        s_att[i][j] = a * 0.125f;  // 64^{-1/2}
    }
    __syncthreads();
    if (tid < T_) {
        int i = tid;
        float m = -1e30f;
        for (int j = 0; j < T_; j++) m = fmaxf(m, s_att[i][j]);
        float sum = 0.f;
        for (int j = 0; j < T_; j++) { float e = __expf(s_att[i][j] - m); s_att[i][j] = e; sum += e; }
        float inv = 1.f / sum;
        for (int j = 0; j < T_; j++) s_att[i][j] *= inv;
    }
    __syncthreads();
    // o[d][t] = sum_j att[t][j] * v[d][j]
    for (int idx = tid; idx < CR_*T_; idx += 256) {
        int d = idx >> 3, t = idx & 7;
        float a = 0.f;
        for (int j = 0; j < T_; j++) a += s_att[t][j] * s_qkv[2*CR_ + d][j];
        s_o[d][t] = a;
    }
    __syncthreads();
    // ao proj + residual -> reuse s_x1 as x3
    for (int idx = tid; idx < CR_*T_; idx += 256) {
        int r = idx >> 3, t = idx & 7;
        float acc = ao_b[r];
        const float* w = ao_w + (size_t)r * CR_;
        for (int c = 0; c < CR_; c++) acc += w[c] * s_o[c][t];
        s_x1[r][t] = s_x2[r][t] + acc;
    }
    __syncthreads();

    // w_alpha / b_alpha: [256][8] each, conv1d k=3 pad=1 over t, no bias
    for (int idx = tid; idx < C_*T_; idx += 256) {
        int Co = idx >> 3, t = idx & 7;
        float aw = 0.f, ab = 0.f;
        const float* w1base = b_w  + (size_t)Co * CR_ * 3;
        const float* w2base = bb_w + (size_t)Co * CR_ * 3;
        for (int r = 0; r < CR_; r++) {
            float x0 = (t > 0) ? s_x1[r][t-1] : 0.f;
            float x1 = s_x1[r][t];
            float x2 = (t < 7) ? s_x1[r][t+1] : 0.f;
            const float* w1 = w1base + r*3;
            const float* w2 = w2base + r*3;
            aw += w1[0]*x0 + w1[1]*x1 + w1[2]*x2;
            ab += w2[0]*x0 + w2[1]*x1 + w2[2]*x2;
        }
        g_walpha[b*C_*T_ + idx] = aw;
        g_balpha[b*C_*T_ + idx] = ab;
    }
}

// ---------------------------------------------------------------------------
// Kernel 3: calibrated 3x3 conv.
// grid: x = h-tile (7 tiles of 8 rows), y = o-group (16 groups of 16),
//       z = b*t (64). block: 224 threads.
// thread: othr = tid/112 (8 o each), spatial 2x2 pixels.
// ---------------------------------------------------------------------------
#define CCHUNK 4
__global__ void __launch_bounds__(224)
conv_kernel(const float* __restrict__ feat, const float* __restrict__ Wt,
            const float* __restrict__ bias_p)
{
    int bt = blockIdx.z;
    int b  = bt >> 3, t = bt & 7;
    int og = blockIdx.y;        // output-channel group (16 ch)
    int yt = blockIdx.x;        // row tile (8 rows)
    int tid = threadIdx.x;
    int othr = tid / 112;       // 0..1
    int sp   = tid % 112;
    int sx = sp % 28;           // 0..27 (column pair)
    int sy = sp / 28;           // 0..3  (row pair)
    int px = 2*sx;
    int py = yt*8 + 2*sy;

    __shared__ float s_in[CCHUNK][10][58];
    __shared__ float s_w[16][CCHUNK][9];

    float acc[8][2][2] = {};

    const size_t cstride = (size_t)T_ * HW_;
    const float* fbase = feat + ((size_t)b * C_ * T_ + t) * HW_;
    const float* wa    = g_walpha + b*C_*T_ + t;     // + c*8

    for (int c0 = 0; c0 < C_; c0 += CCHUNK) {
        // load scaled input tile: CCHUNK x 10 x 58
        for (int idx = tid; idx < CCHUNK*10*58; idx += 224) {
            int cc  = idx / 580;
            int rem = idx % 580;
            int ly  = rem / 58;
            int lx  = rem % 58;
            int gy = yt*8 + ly - 1;
            int gx = lx - 1;
            float v = 0.f;
            if (gy >= 0 && gy < H_ && gx >= 0 && gx < W_) {
                v = fbase[(size_t)(c0+cc)*cstride + gy*W_ + gx] * wa[(c0+cc)*T_];
            }
            s_in[cc][ly][lx] = v;
        }
        // load weights: 16 x CCHUNK x 9
        for (int idx = tid; idx < 16*CCHUNK*9; idx += 224) {
            int oo  = idx / (CCHUNK*9);
            int rem = idx % (CCHUNK*9);
            int cc  = rem / 9;
            int k   = rem % 9;
            s_w[oo][cc][k] = Wt[((size_t)(og*16 + oo) * C_ + c0 + cc) * 9 + k];
        }
        __syncthreads();

        #pragma unroll
        for (int cc = 0; cc < CCHUNK; cc++) {
            float in[4][4];
            #pragma unroll
            for (int r = 0; r < 4; r++)
                #pragma unroll
                for (int cI = 0; cI < 4; cI++)
                    in[r][cI] = s_in[cc][2*sy + r][2*sx + cI];

            #pragma unroll
            for (int oo = 0; oo < 8; oo++) {
                const float* wp = &s_w[othr*8 + oo][cc][0];
                float w0 = wp[0], w1 = wp[1], w2 = wp[2];
                float w3 = wp[3], w4 = wp[4], w5 = wp[5];
                float w6 = wp[6], w7 = wp[7], w8 = wp[8];
                #pragma unroll
                for (int dy = 0; dy < 2; dy++)
                    #pragma unroll
                    for (int dx = 0; dx < 2; dx++) {
                        float a = acc[oo][dy][dx];
                        a = fmaf(w0, in[dy  ][dx  ], a);
                        a = fmaf(w1, in[dy  ][dx+1], a);
                        a = fmaf(w2, in[dy  ][dx+2], a);
                        a = fmaf(w3, in[dy+1][dx  ], a);
                        a = fmaf(w4, in[dy+1][dx+1], a);
                        a = fmaf(w5, in[dy+1][dx+2], a);
                        a = fmaf(w6, in[dy+2][dx  ], a);
                        a = fmaf(w7, in[dy+2][dx+1], a);
                        a = fmaf(w8, in[dy+2][dx+2], a);
                        acc[oo][dy][dx] = a;
                    }
            }
        }
        __syncthreads();
    }

    // epilogue: bias + store to scratch
    #pragma unroll
    for (int oo = 0; oo < 8; oo++) {
        int o = og*16 + othr*8 + oo;
        float bias = g_balpha[b*C_*T_ + o*T_ + t] * bias_p[o];
        size_t obase = (((size_t)b*C_ + o)*T_ + t) * HW_;
        #pragma unroll
        for (int dy = 0; dy < 2; dy++)
            #pragma unroll
            for (int dx = 0; dx < 2; dx++)
                g_conv[obase + (py+dy)*W_ + (px+dx)] = acc[oo][dy][dx] + bias;
    }
}

// ---------------------------------------------------------------------------
// Kernel 4a: zero stats
// ---------------------------------------------------------------------------
__global__ void zero_stats_kernel() {
    int i = threadIdx.x + blockIdx.x * blockDim.x;
    if (i < C_*4) ((double*)g_stats)[i] = 0.0;
}

// ---------------------------------------------------------------------------
// Kernel 4: per-channel stats of conv output and its temporal 3-tap average
// grid: (98, 256 channels), 256 threads; each thread: fixed (b,hw), loop t.
// ---------------------------------------------------------------------------
__global__ void stats_kernel() {
    int c = blockIdx.y;
    int item = blockIdx.x * blockDim.x + threadIdx.x;   // 0..25087
    int b  = item / HW_;
    int hw = item % HW_;

    size_t base = (((size_t)b*C_ + c)*T_) * HW_ + hw;
    float so = 0.f, sq = 0.f, sa = 0.f, sqa = 0.f;
    float prev = 0.f;
    float cur  = g_conv[base];
    #pragma unroll
    for (int t = 0; t < T_; t++) {
        float next = (t < T_-1) ? g_conv[base + (size_t)(t+1)*HW_] : 0.f;
        so += cur;
        sq += cur*cur;
        float ap = (prev + cur + next) * (1.f/3.f);
        sa  += ap;
        sqa += ap*ap;
        prev = cur; cur = next;
    }

    // block reduce 4 floats
    __shared__ float sb[4][8];
    #pragma unroll
    for (int o = 16; o; o >>= 1) {
        so  += __shfl_down_sync(0xffffffffu, so,  o);
        sq  += __shfl_down_sync(0xffffffffu, sq,  o);
        sa  += __shfl_down_sync(0xffffffffu, sa,  o);
        sqa += __shfl_down_sync(0xffffffffu, sqa, o);
    }
    int lane = threadIdx.x & 31, w = threadIdx.x >> 5;
    if (lane == 0) { sb[0][w] = so; sb[1][w] = sq; sb[2][w] = sa; sb[3][w] = sqa; }
    __syncthreads();
    if (threadIdx.x == 0) {
        float a0=0, a1=0, a2=0, a3=0;
        for (int i = 0; i < 8; i++) { a0+=sb[0][i]; a1+=sb[1][i]; a2+=sb[2][i]; a3+=sb[3][i]; }
        atomicAdd(&g_stats[c][0], (double)a0);
        atomicAdd(&g_stats[c][1], (double)a1);
        atomicAdd(&g_stats[c][2], (double)a2);
        atomicAdd(&g_stats[c][3], (double)a3);
    }
}

// ---------------------------------------------------------------------------
// Kernel 5: final  out = bn_a(conv) + bn_b(avgpool_t3(conv))
// ---------------------------------------------------------------------------
__global__ void final_kernel(const float* __restrict__ gamma_a, const float* __restrict__ beta_a,
                             const float* __restrict__ gamma_b, const float* __restrict__ beta_b,
                             float* __restrict__ out)
{
    int c = blockIdx.y;
    int item = blockIdx.x * blockDim.x + threadIdx.x;
    int b  = item / HW_;
    int hw = item % HW_;

    const double N = (double)B_ * T_ * HW_;
    double mu_a = g_stats[c][0] / N;
    double va   = g_stats[c][1] / N - mu_a*mu_a;
    double mu_b = g_stats[c][2] / N;
    double vb   = g_stats[c][3] / N - mu_b*mu_b;
    float sca = gamma_a[c] * (float)(1.0 / sqrt(va + 1e-5));
    float sha = beta_a[c] - (float)mu_a * sca;
    float scb = gamma_b[c] * (float)(1.0 / sqrt(vb + 1e-5));
    float shb = beta_b[c] - (float)mu_b * scb;

    size_t base = (((size_t)b*C_ + c)*T_) * HW_ + hw;
    float prev = 0.f;
    float cur  = g_conv[base];
    #pragma unroll
    for (int t = 0; t < T_; t++) {
        float next = (t < T_-1) ? g_conv[base + (size_t)(t+1)*HW_] : 0.f;
        float ap = (prev + cur + next) * (1.f/3.f);
        out[base + (size_t)t*HW_] = cur*sca + sha + ap*scb + shb;
        prev = cur; cur = next;
    }
}

// ---------------------------------------------------------------------------
extern "C" void kernel_launch(void* const* d_in, const int* in_sizes, int n_in,
                              void* d_out, int out_size)
{
    const float* feat    = (const float*)d_in[0];
    const float* Wt      = (const float*)d_in[1];
    const float* bias_p  = (const float*)d_in[2];
    const float* a_w     = (const float*)d_in[3];
    const float* a_b     = (const float*)d_in[4];
    const float* norm_w  = (const float*)d_in[5];
    const float* norm_b  = (const float*)d_in[6];
    const float* normt_w = (const float*)d_in[7];
    const float* normt_b = (const float*)d_in[8];
    const float* qkv_w   = (const float*)d_in[9];
    const float* qkv_b   = (const float*)d_in[10];
    const float* ao_w    = (const float*)d_in[11];
    const float* ao_b    = (const float*)d_in[12];
    const float* b_w     = (const float*)d_in[13];
    const float* bb_w    = (const float*)d_in[14];
    const float* gamma_a = (const float*)d_in[15];
    const float* beta_a  = (const float*)d_in[16];
    const float* gamma_b = (const float*)d_in[17];
    const float* beta_b  = (const float*)d_in[18];
    float* out = (float*)d_out;

    pool_kernel<<<B_*C_*T_, 128>>>(feat);
    routing_kernel<<<B_, 256>>>(a_w, a_b, norm_w, norm_b, normt_w, normt_b,
                                qkv_w, qkv_b, ao_w, ao_b, b_w, bb_w);
    conv_kernel<<<dim3(7, 16, 64), 224>>>(feat, Wt, bias_p);
    zero_stats_kernel<<<4, 256>>>();
    stats_kernel<<<dim3(98, 256), 256>>>();
    final_kernel<<<dim3(98, 256), 256>>>(gamma_a, beta_a, gamma_b, beta_b, out);
}

// round 5
// speedup vs baseline: 3.9181x; 3.9181x over previous
#include <cuda_runtime.h>
#include <cuda_bf16.h>
#include <math.h>
#include <stdint.h>

#define B_  8
#define C_  256
#define T_  8
#define H_  56
#define W_  56
#define HW_ (H_*W_)
#define CR_ 64
#define PR_ 58
#define PC_ 64
#define PXI_ (PR_*PC_)     // 3712
#define NIMG 64
#define AST 36             // padded smem row stride (floats)

__device__ float  g_pool[B_*C_*T_];
__device__ float  g_walpha[B_*C_*T_];
__device__ float  g_balpha[B_*C_*T_];
__device__ float  g_conv[(size_t)B_*C_*T_*HW_];
__device__ double g_stats[C_][4];
__device__ float  g_xs[(size_t)NIMG*PXI_*C_];     // padded NHWC, tf32-rounded
__device__ float  g_wp[9*8*256*32];               // [tap][cchunk][o][cc], tf32-rounded

// ---------------- helpers ----------------
__device__ __forceinline__ uint32_t smem_to_u32(const void* p) {
    uint32_t a;
    asm("{ .reg .u64 t; cvta.to.shared.u64 t, %1; cvt.u32.u64 %0, t; }" : "=r"(a) : "l"(p));
    return a;
}
__device__ __forceinline__ void cp_async16(uint32_t dst, const void* src) {
    asm volatile("cp.async.ca.shared.global [%0], [%1], 16;" :: "r"(dst), "l"(src));
}
#define CP_COMMIT()  asm volatile("cp.async.commit_group;" ::: "memory")
#define CP_WAIT_ALL() asm volatile("cp.async.wait_all;" ::: "memory")
#define CP_WAIT0()   asm volatile("cp.async.wait_group 0;" ::: "memory")

__device__ __forceinline__ void mma_tf32(float* c, const uint32_t* a, uint32_t b0, uint32_t b1) {
    asm volatile("mma.sync.aligned.m16n8k8.row.col.f32.tf32.tf32.f32 "
        "{%0,%1,%2,%3}, {%4,%5,%6,%7}, {%8,%9}, {%0,%1,%2,%3};"
        : "+f"(c[0]), "+f"(c[1]), "+f"(c[2]), "+f"(c[3])
        : "r"(a[0]), "r"(a[1]), "r"(a[2]), "r"(a[3]), "r"(b0), "r"(b1));
}
__device__ __forceinline__ float totf32(float x) {
    uint32_t u; asm("cvt.rna.tf32.f32 %0, %1;" : "=r"(u) : "f"(x));
    return __uint_as_float(u);
}
__device__ __forceinline__ float qgelu(float x) { return x / (1.f + __expf(-1.702f * x)); }

// ---------------- pool ----------------
__global__ void pool_kernel(const float* __restrict__ feat) {
    int bct = blockIdx.x;
    const float* p = feat + (size_t)bct * HW_;
    float s = 0.f;
    for (int i = threadIdx.x; i < HW_; i += blockDim.x) s += p[i];
    for (int o = 16; o; o >>= 1) s += __shfl_down_sync(0xffffffffu, s, o);
    __shared__ float sb[8];
    int lane = threadIdx.x & 31, w = threadIdx.x >> 5;
    if (lane == 0) sb[w] = s;
    __syncthreads();
    if (threadIdx.x == 0) {
        float t = 0.f;
        for (int i = 0; i < (int)(blockDim.x >> 5); i++) t += sb[i];
        g_pool[bct] = t * (1.f / HW_);
    }
}

// ---------------- routing (validated in R1) ----------------
__global__ void routing_kernel(
    const float* __restrict__ a_w, const float* __restrict__ a_b,
    const float* __restrict__ norm_w, const float* __restrict__ norm_b,
    const float* __restrict__ normt_w, const float* __restrict__ normt_b,
    const float* __restrict__ qkv_w, const float* __restrict__ qkv_b,
    const float* __restrict__ ao_w, const float* __restrict__ ao_b,
    const float* __restrict__ b_w, const float* __restrict__ bb_w)
{
    int b = blockIdx.x, tid = threadIdx.x;
    __shared__ float s_pool[C_][T_], s_x1[CR_][T_], s_x2[CR_][T_], s_xn[CR_][T_];
    __shared__ float s_qkv[3*CR_][T_], s_att[T_][T_], s_o[CR_][T_], s_mu[T_], s_rstd[T_];

    for (int i = tid; i < C_*T_; i += 256) s_pool[i >> 3][i & 7] = g_pool[b*C_*T_ + i];
    __syncthreads();
    for (int idx = tid; idx < CR_*T_; idx += 256) {
        int r = idx >> 3, t = idx & 7;
        float acc = a_b[r];
        const float* wb = a_w + (size_t)r * C_ * 3;
        for (int c = 0; c < C_; c++) {
            float p0 = (t > 0) ? s_pool[c][t-1] : 0.f, p1 = s_pool[c][t], p2 = (t < 7) ? s_pool[c][t+1] : 0.f;
            const float* w = wb + c*3;
            acc += w[0]*p0 + w[1]*p1 + w[2]*p2;
        }
        s_x1[r][t] = acc;
    }
    __syncthreads();
    if (tid < T_) {
        int t = tid;
        float mu = 0.f;
        for (int r = 0; r < CR_; r++) mu += s_x1[r][t];
        mu *= (1.f / CR_);
        float v = 0.f;
        for (int r = 0; r < CR_; r++) { float d = s_x1[r][t] - mu; v += d*d; }
        s_mu[t] = mu; s_rstd[t] = rsqrtf(v * (1.f / CR_) + 1e-6f);
    }
    __syncthreads();
    for (int idx = tid; idx < CR_*T_; idx += 256) {
        int r = idx >> 3, t = idx & 7;
        s_x2[r][t] = qgelu((s_x1[r][t] - s_mu[t]) * s_rstd[t] * norm_w[r] + norm_b[r]);
    }
    __syncthreads();
    if (tid < T_) {
        int t = tid;
        float mu = 0.f;
        for (int r = 0; r < CR_; r++) mu += s_x2[r][t];
        mu *= (1.f / CR_);
        float v = 0.f;
        for (int r = 0; r < CR_; r++) { float d = s_x2[r][t] - mu; v += d*d; }
        s_mu[t] = mu; s_rstd[t] = rsqrtf(v * (1.f / CR_) + 1e-6f);
    }
    __syncthreads();
    for (int idx = tid; idx < CR_*T_; idx += 256) {
        int r = idx >> 3, t = idx & 7;
        s_xn[r][t] = (s_x2[r][t] - s_mu[t]) * s_rstd[t] * normt_w[r] + normt_b[r];
    }
    __syncthreads();
    for (int idx = tid; idx < 3*CR_*T_; idx += 256) {
        int o = idx >> 3, t = idx & 7;
        float acc = qkv_b[o];
        const float* w = qkv_w + (size_t)o * CR_;
        for (int c = 0; c < CR_; c++) acc += w[c] * s_xn[c][t];
        s_qkv[o][t] = acc;
    }
    __syncthreads();
    if (tid < T_*T_) {
        int i = tid >> 3, j = tid & 7;
        float a = 0.f;
        for (int d = 0; d < CR_; d++) a += s_qkv[d][i] * s_qkv[CR_ + d][j];
        s_att[i][j] = a * 0.125f;
    }
    __syncthreads();
    if (tid < T_) {
        int i = tid;
        float m = -1e30f;
        for (int j = 0; j < T_; j++) m = fmaxf(m, s_att[i][j]);
        float sum = 0.f;
        for (int j = 0; j < T_; j++) { float e = __expf(s_att[i][j] - m); s_att[i][j] = e; sum += e; }
        float inv = 1.f / sum;
        for (int j = 0; j < T_; j++) s_att[i][j] *= inv;
    }
    __syncthreads();
    for (int idx = tid; idx < CR_*T_; idx += 256) {
        int d = idx >> 3, t = idx & 7;
        float a = 0.f;
        for (int j = 0; j < T_; j++) a += s_att[t][j] * s_qkv[2*CR_ + d][j];
        s_o[d][t] = a;
    }
    __syncthreads();
    for (int idx = tid; idx < CR_*T_; idx += 256) {
        int r = idx >> 3, t = idx & 7;
        float acc = ao_b[r];
        const float* w = ao_w + (size_t)r * CR_;
        for (int c = 0; c < CR_; c++) acc += w[c] * s_o[c][t];
        s_x1[r][t] = s_x2[r][t] + acc;
    }
    __syncthreads();
    for (int idx = tid; idx < C_*T_; idx += 256) {
        int Co = idx >> 3, t = idx & 7;
        float aw = 0.f, ab = 0.f;
        const float* w1b = b_w  + (size_t)Co * CR_ * 3;
        const float* w2b = bb_w + (size_t)Co * CR_ * 3;
        for (int r = 0; r < CR_; r++) {
            float x0 = (t > 0) ? s_x1[r][t-1] : 0.f, x1 = s_x1[r][t], x2 = (t < 7) ? s_x1[r][t+1] : 0.f;
            const float* w1 = w1b + r*3;
            const float* w2 = w2b + r*3;
            aw += w1[0]*x0 + w1[1]*x1 + w1[2]*x2;
            ab += w2[0]*x0 + w2[1]*x1 + w2[2]*x2;
        }
        g_walpha[b*C_*T_ + idx] = aw;
        g_balpha[b*C_*T_ + idx] = ab;
    }
}

// ---- weight prepack: g_wp[((tap*8+kc)*256 + o)*32 + cc] = tf32(W[o][kc*32+cc][ky][kx]) ----
__global__ void prepack_w_kernel(const float* __restrict__ Wt) {
    int idx = blockIdx.x * 256 + threadIdx.x;   // < 589824
    int cc = idx & 31, o = (idx >> 5) & 255, kc = (idx >> 13) & 7, tap = idx >> 16;
    int ky = tap / 3, kx = tap % 3;
    g_wp[idx] = totf32(Wt[(((size_t)o*C_ + kc*32 + cc)*3 + ky)*3 + kx]);
}

// ---- stage scaled input -> padded NHWC tf32: g_xs[(img*PXI + r*64 + x)*256 + c] ----
__global__ void stage_xs_kernel(const float* __restrict__ feat) {
    __shared__ float s[32][65];
    int img = blockIdx.z, r = blockIdx.y, c0 = blockIdx.x * 32;
    int b = img >> 3, t = img & 7;
    int tid = threadIdx.x;
    int x = tid & 63, cl0 = tid >> 6;
    for (int cl = cl0; cl < 32; cl += 4) {
        float v = 0.f;
        if (r >= 1 && r <= 56 && x >= 1 && x <= 56) {
            int c = c0 + cl;
            v = feat[(((size_t)(b*C_ + c))*T_ + t)*HW_ + (r-1)*W_ + (x-1)] * g_walpha[(b*C_ + c)*T_ + t];
        }
        s[cl][x] = totf32(v);
    }
    __syncthreads();
    int k = tid & 31, x0 = tid >> 5;
    for (int xx = x0; xx < 64; xx += 8)
        g_xs[((size_t)img*PXI_ + r*PC_ + xx)*C_ + c0 + k] = s[k][xx];
}

// ---------------- conv: implicit GEMM via mma.sync tf32 ----------------
// grid (28 ytiles, 64 imgs), 256 threads. Block: M=128 (2 out rows), N=256, K=9*256.
#define SMEM_FLOATS (256 + 258*AST + 2*256*AST)
__global__ void __launch_bounds__(256, 1)
conv_mma_kernel(const float* __restrict__ bias_p)
{
    extern __shared__ float sm[];
    float* bias_sm = sm;                 // 256
    float* As = sm + 256;                // 258*36
    float* Bs = As + 258*AST;            // 2 * 256*36
    uint32_t as_u = smem_to_u32(As);
    uint32_t bs_u = smem_to_u32(Bs);

    int tid = threadIdx.x, lane = tid & 31, wid = tid >> 5;
    int wm = wid >> 2, wn = wid & 3;     // warp 2x4 (M x N)
    int mg = lane >> 2, tg = lane & 3;
    int img = blockIdx.y, yt = blockIdx.x;
    int b = img >> 3, t = img & 7;
    size_t imgP = (size_t)img * PXI_ + (size_t)yt * 128;   // base pixel (2 padded rows)

    if (tid < 256)
        bias_sm[tid] = g_balpha[(b*C_ + tid)*T_ + t] * bias_p[tid];

    float acc[4][8][4] = {};

    for (int kc = 0; kc < 8; kc++) {
        // stage A: 258 pixel-rows x 32 ch (covers all tap shifts: off in [0,130])
        const float* srcA = g_xs + imgP*C_ + kc*32;
        for (int idx = tid; idx < 258*8; idx += 256) {
            int p = idx >> 3, kq = idx & 7;
            cp_async16(as_u + (uint32_t)(p*AST + kq*4)*4, srcA + (size_t)p*C_ + kq*4);
        }
        // stage B tap0 -> buf0
        {
            const float* srcB = g_wp + (size_t)kc*8192;
            for (int idx = tid; idx < 2048; idx += 256)
                cp_async16(bs_u + (uint32_t)((idx>>3)*AST + (idx&7)*4)*4, srcB + idx*4);
        }
        CP_COMMIT(); CP_WAIT_ALL();
        __syncthreads();

        for (int tap = 0; tap < 9; tap++) {
            int buf = tap & 1;
            if (tap < 8) {      // prefetch next B into other buffer
                const float* srcB = g_wp + (size_t)((tap+1)*8 + kc)*8192;
                uint32_t dstb = bs_u + (uint32_t)((buf^1)*256*AST)*4;
                for (int idx = tid; idx < 2048; idx += 256)
                    cp_async16(dstb + (uint32_t)((idx>>3)*AST + (idx&7)*4)*4, srcB + idx*4);
                CP_COMMIT();
            }
            int off = (tap/3)*64 + (tap%3);          // A row shift for this tap
            const float* Bbuf = Bs + buf*256*AST;
            #pragma unroll
            for (int ks = 0; ks < 4; ks++) {
                int k0 = ks*8;
                uint32_t af[4][4];
                #pragma unroll
                for (int i = 0; i < 4; i++) {
                    int rb = off + wm*64 + i*16 + mg;
                    af[i][0] = __float_as_uint(As[rb*AST + k0 + tg]);
                    af[i][1] = __float_as_uint(As[(rb+8)*AST + k0 + tg]);
                    af[i][2] = __float_as_uint(As[rb*AST + k0 + tg + 4]);
                    af[i][3] = __float_as_uint(As[(rb+8)*AST + k0 + tg + 4]);
                }
                #pragma unroll
                for (int j = 0; j < 8; j++) {
                    int nb = wn*64 + j*8 + mg;
                    uint32_t b0 = __float_as_uint(Bbuf[nb*AST + k0 + tg]);
                    uint32_t b1 = __float_as_uint(Bbuf[nb*AST + k0 + tg + 4]);
                    #pragma unroll
                    for (int i = 0; i < 4; i++)
                        mma_tf32(acc[i][j], af[i], b0, b1);
                }
            }
            if (tap < 8) CP_WAIT0();
            __syncthreads();
        }
    }

    // epilogue: acc -> g_conv (NCTHW) + bias; 32B-contiguous store segments
    #pragma unroll
    for (int i = 0; i < 4; i++) {
        #pragma unroll
        for (int j = 0; j < 8; j++) {
            #pragma unroll
            for (int e = 0; e < 4; e++) {
                int m = wm*64 + i*16 + mg + (e>>1)*8;
                int n = wn*64 + j*8 + tg*2 + (e&1);
                int x = m & 63;
                if (x < 56) {
                    int y = yt*2 + (m>>6);
                    g_conv[(((size_t)(b*C_ + n))*T_ + t)*HW_ + y*W_ + x] = acc[i][j][e] + bias_sm[n];
                }
            }
        }
    }
}

// ---------------- stats + final ----------------
__global__ void zero_stats_kernel() {
    int i = threadIdx.x + blockIdx.x * blockDim.x;
    if (i < C_*4) ((double*)g_stats)[i] = 0.0;
}
__global__ void stats_kernel() {
    int c = blockIdx.y;
    int item = blockIdx.x * blockDim.x + threadIdx.x;
    int b = item / HW_, hw = item % HW_;
    size_t base = (((size_t)b*C_ + c)*T_) * HW_ + hw;
    float so = 0.f, sq = 0.f, sa = 0.f, sqa = 0.f, prev = 0.f, cur = g_conv[base];
    #pragma unroll
    for (int t = 0; t < T_; t++) {
        float nxt = (t < T_-1) ? g_conv[base + (size_t)(t+1)*HW_] : 0.f;
        so += cur; sq += cur*cur;
        float ap = (prev + cur + nxt) * (1.f/3.f);
        sa += ap; sqa += ap*ap;
        prev = cur; cur = nxt;
    }
    __shared__ float sb[4][8];
    for (int o = 16; o; o >>= 1) {
        so += __shfl_down_sync(0xffffffffu, so, o);
        sq += __shfl_down_sync(0xffffffffu, sq, o);
        sa += __shfl_down_sync(0xffffffffu, sa, o);
        sqa += __shfl_down_sync(0xffffffffu, sqa, o);
    }
    int lane = threadIdx.x & 31, w = threadIdx.x >> 5;
    if (lane == 0) { sb[0][w] = so; sb[1][w] = sq; sb[2][w] = sa; sb[3][w] = sqa; }
    __syncthreads();
    if (threadIdx.x == 0) {
        float a0=0, a1=0, a2=0, a3=0;
        for (int i = 0; i < 8; i++) { a0+=sb[0][i]; a1+=sb[1][i]; a2+=sb[2][i]; a3+=sb[3][i]; }
        atomicAdd(&g_stats[c][0], (double)a0);
        atomicAdd(&g_stats[c][1], (double)a1);
        atomicAdd(&g_stats[c][2], (double)a2);
        atomicAdd(&g_stats[c][3], (double)a3);
    }
}
__global__ void final_kernel(const float* __restrict__ gamma_a, const float* __restrict__ beta_a,
                             const float* __restrict__ gamma_b, const float* __restrict__ beta_b,
                             float* __restrict__ out)
{
    int c = blockIdx.y;
    int item = blockIdx.x * blockDim.x + threadIdx.x;
    int b = item / HW_, hw = item % HW_;
    const double N = (double)B_ * T_ * HW_;
    double mu_a = g_stats[c][0] / N, va = g_stats[c][1] / N - mu_a*mu_a;
    double mu_b = g_stats[c][2] / N, vb = g_stats[c][3] / N - mu_b*mu_b;
    float sca = gamma_a[c] * (float)(1.0 / sqrt(va + 1e-5));
    float sha = beta_a[c] - (float)mu_a * sca;
    float scb = gamma_b[c] * (float)(1.0 / sqrt(vb + 1e-5));
    float shb = beta_b[c] - (float)mu_b * scb;
    size_t base = (((size_t)b*C_ + c)*T_) * HW_ + hw;
    float prev = 0.f, cur = g_conv[base];
    #pragma unroll
    for (int t = 0; t < T_; t++) {
        float nxt = (t < T_-1) ? g_conv[base + (size_t)(t+1)*HW_] : 0.f;
        float ap = (prev + cur + nxt) * (1.f/3.f);
        out[base + (size_t)t*HW_] = cur*sca + sha + ap*scb + shb;
        prev = cur; cur = nxt;
    }
}

// ---------------------------------------------------------------------------
extern "C" void kernel_launch(void* const* d_in, const int* in_sizes, int n_in,
                              void* d_out, int out_size)
{
    const float* feat    = (const float*)d_in[0];
    const float* Wt      = (const float*)d_in[1];
    const float* bias_p  = (const float*)d_in[2];
    const float* a_w     = (const float*)d_in[3];
    const float* a_b     = (const float*)d_in[4];
    const float* norm_w  = (const float*)d_in[5];
    const float* norm_b  = (const float*)d_in[6];
    const float* normt_w = (const float*)d_in[7];
    const float* normt_b = (const float*)d_in[8];
    const float* qkv_w   = (const float*)d_in[9];
    const float* qkv_b   = (const float*)d_in[10];
    const float* ao_w    = (const float*)d_in[11];
    const float* ao_b    = (const float*)d_in[12];
    const float* b_w     = (const float*)d_in[13];
    const float* bb_w    = (const float*)d_in[14];
    const float* gamma_a = (const float*)d_in[15];
    const float* beta_a  = (const float*)d_in[16];
    const float* gamma_b = (const float*)d_in[17];
    const float* beta_b  = (const float*)d_in[18];
    float* out = (float*)d_out;

    static int smem_set = 0;
    if (!smem_set) {
        cudaFuncSetAttribute(conv_mma_kernel, cudaFuncAttributeMaxDynamicSharedMemorySize,
                             SMEM_FLOATS * 4);
        smem_set = 1;
    }

    pool_kernel<<<B_*C_*T_, 128>>>(feat);
    routing_kernel<<<B_, 256>>>(a_w, a_b, norm_w, norm_b, normt_w, normt_b,
                                qkv_w, qkv_b, ao_w, ao_b, b_w, bb_w);
    prepack_w_kernel<<<2304, 256>>>(Wt);
    stage_xs_kernel<<<dim3(8, PR_, NIMG), 256>>>(feat);
    conv_mma_kernel<<<dim3(28, NIMG), 256, SMEM_FLOATS * 4>>>(bias_p);
    zero_stats_kernel<<<4, 256>>>();
    stats_kernel<<<dim3(98, 256), 256>>>();
    final_kernel<<<dim3(98, 256), 256>>>(gamma_a, beta_a, gamma_b, beta_b, out);
}

// round 6
// speedup vs baseline: 3.9237x; 1.0014x over previous
#include <cuda_runtime.h>
#include <cuda_bf16.h>
#include <math.h>
#include <stdint.h>

#define B_  8
#define C_  256
#define T_  8
#define H_  56
#define W_  56
#define HW_ (H_*W_)
#define CR_ 64
#define PR_ 58
#define PC_ 64
#define PXI_ (PR_*PC_)     // 3712
#define NIMG 64
#define AST 36             // padded smem row stride (floats)

__device__ float  g_pool[B_*C_*T_];
__device__ float  g_walpha[B_*C_*T_];
__device__ float  g_balpha[B_*C_*T_];
__device__ float  g_conv[(size_t)B_*C_*T_*HW_];
__device__ double g_stats[C_][4];
__device__ float  g_xs[(size_t)NIMG*PXI_*C_];     // padded NHWC, tf32-rounded
__device__ float  g_wp[9*8*256*32];               // [tap][cchunk][o][cc], tf32-rounded

// ---------------- helpers ----------------
__device__ __forceinline__ uint32_t smem_to_u32(const void* p) {
    uint32_t a;
    asm("{ .reg .u64 t; cvta.to.shared.u64 t, %1; cvt.u32.u64 %0, t; }" : "=r"(a) : "l"(p));
    return a;
}
__device__ __forceinline__ void cp_async16(uint32_t dst, const void* src) {
    asm volatile("cp.async.ca.shared.global [%0], [%1], 16;" :: "r"(dst), "l"(src));
}
#define CP_COMMIT()  asm volatile("cp.async.commit_group;" ::: "memory")
#define CP_WAIT_ALL() asm volatile("cp.async.wait_all;" ::: "memory")
#define CP_WAIT0()   asm volatile("cp.async.wait_group 0;" ::: "memory")

__device__ __forceinline__ void mma_tf32(float* c, const uint32_t* a, uint32_t b0, uint32_t b1) {
    asm volatile("mma.sync.aligned.m16n8k8.row.col.f32.tf32.tf32.f32 "
        "{%0,%1,%2,%3}, {%4,%5,%6,%7}, {%8,%9}, {%0,%1,%2,%3};"
        : "+f"(c[0]), "+f"(c[1]), "+f"(c[2]), "+f"(c[3])
        : "r"(a[0]), "r"(a[1]), "r"(a[2]), "r"(a[3]), "r"(b0), "r"(b1));
}
__device__ __forceinline__ float totf32(float x) {
    uint32_t u; asm("cvt.rna.tf32.f32 %0, %1;" : "=r"(u) : "f"(x));
    return __uint_as_float(u);
}
__device__ __forceinline__ float qgelu(float x) { return x / (1.f + __expf(-1.702f * x)); }

// ---------------- pool ----------------
__global__ void pool_kernel(const float* __restrict__ feat) {
    int bct = blockIdx.x;
    const float* p = feat + (size_t)bct * HW_;
    float s = 0.f;
    for (int i = threadIdx.x; i < HW_; i += blockDim.x) s += p[i];
    for (int o = 16; o; o >>= 1) s += __shfl_down_sync(0xffffffffu, s, o);
    __shared__ float sb[8];
    int lane = threadIdx.x & 31, w = threadIdx.x >> 5;
    if (lane == 0) sb[w] = s;
    __syncthreads();
    if (threadIdx.x == 0) {
        float t = 0.f;
        for (int i = 0; i < (int)(blockDim.x >> 5); i++) t += sb[i];
        g_pool[bct] = t * (1.f / HW_);
    }
}

// ---------------- routing (validated in R1) ----------------
__global__ void routing_kernel(
    const float* __restrict__ a_w, const float* __restrict__ a_b,
    const float* __restrict__ norm_w, const float* __restrict__ norm_b,
    const float* __restrict__ normt_w, const float* __restrict__ normt_b,
    const float* __restrict__ qkv_w, const float* __restrict__ qkv_b,
    const float* __restrict__ ao_w, const float* __restrict__ ao_b,
    const float* __restrict__ b_w, const float* __restrict__ bb_w)
{
    int b = blockIdx.x, tid = threadIdx.x;
    __shared__ float s_pool[C_][T_], s_x1[CR_][T_], s_x2[CR_][T_], s_xn[CR_][T_];
    __shared__ float s_qkv[3*CR_][T_], s_att[T_][T_], s_o[CR_][T_], s_mu[T_], s_rstd[T_];

    for (int i = tid; i < C_*T_; i += 256) s_pool[i >> 3][i & 7] = g_pool[b*C_*T_ + i];
    __syncthreads();
    for (int idx = tid; idx < CR_*T_; idx += 256) {
        int r = idx >> 3, t = idx & 7;
        float acc = a_b[r];
        const float* wb = a_w + (size_t)r * C_ * 3;
        for (int c = 0; c < C_; c++) {
            float p0 = (t > 0) ? s_pool[c][t-1] : 0.f, p1 = s_pool[c][t], p2 = (t < 7) ? s_pool[c][t+1] : 0.f;
            const float* w = wb + c*3;
            acc += w[0]*p0 + w[1]*p1 + w[2]*p2;
        }
        s_x1[r][t] = acc;
    }
    __syncthreads();
    if (tid < T_) {
        int t = tid;
        float mu = 0.f;
        for (int r = 0; r < CR_; r++) mu += s_x1[r][t];
        mu *= (1.f / CR_);
        float v = 0.f;
        for (int r = 0; r < CR_; r++) { float d = s_x1[r][t] - mu; v += d*d; }
        s_mu[t] = mu; s_rstd[t] = rsqrtf(v * (1.f / CR_) + 1e-6f);
    }
    __syncthreads();
    for (int idx = tid; idx < CR_*T_; idx += 256) {
        int r = idx >> 3, t = idx & 7;
        s_x2[r][t] = qgelu((s_x1[r][t] - s_mu[t]) * s_rstd[t] * norm_w[r] + norm_b[r]);
    }
    __syncthreads();
    if (tid < T_) {
        int t = tid;
        float mu = 0.f;
        for (int r = 0; r < CR_; r++) mu += s_x2[r][t];
        mu *= (1.f / CR_);
        float v = 0.f;
        for (int r = 0; r < CR_; r++) { float d = s_x2[r][t] - mu; v += d*d; }
        s_mu[t] = mu; s_rstd[t] = rsqrtf(v * (1.f / CR_) + 1e-6f);
    }
    __syncthreads();
    for (int idx = tid; idx < CR_*T_; idx += 256) {
        int r = idx >> 3, t = idx & 7;
        s_xn[r][t] = (s_x2[r][t] - s_mu[t]) * s_rstd[t] * normt_w[r] + normt_b[r];
    }
    __syncthreads();
    for (int idx = tid; idx < 3*CR_*T_; idx += 256) {
        int o = idx >> 3, t = idx & 7;
        float acc = qkv_b[o];
        const float* w = qkv_w + (size_t)o * CR_;
        for (int c = 0; c < CR_; c++) acc += w[c] * s_xn[c][t];
        s_qkv[o][t] = acc;
    }
    __syncthreads();
    if (tid < T_*T_) {
        int i = tid >> 3, j = tid & 7;
        float a = 0.f;
        for (int d = 0; d < CR_; d++) a += s_qkv[d][i] * s_qkv[CR_ + d][j];
        s_att[i][j] = a * 0.125f;
    }
    __syncthreads();
    if (tid < T_) {
        int i = tid;
        float m = -1e30f;
        for (int j = 0; j < T_; j++) m = fmaxf(m, s_att[i][j]);
        float sum = 0.f;
        for (int j = 0; j < T_; j++) { float e = __expf(s_att[i][j] - m); s_att[i][j] = e; sum += e; }
        float inv = 1.f / sum;
        for (int j = 0; j < T_; j++) s_att[i][j] *= inv;
    }
    __syncthreads();
    for (int idx = tid; idx < CR_*T_; idx += 256) {
        int d = idx >> 3, t = idx & 7;
        float a = 0.f;
        for (int j = 0; j < T_; j++) a += s_att[t][j] * s_qkv[2*CR_ + d][j];
        s_o[d][t] = a;
    }
    __syncthreads();
    for (int idx = tid; idx < CR_*T_; idx += 256) {
        int r = idx >> 3, t = idx & 7;
        float acc = ao_b[r];
        const float* w = ao_w + (size_t)r * CR_;
        for (int c = 0; c < CR_; c++) acc += w[c] * s_o[c][t];
        s_x1[r][t] = s_x2[r][t] + acc;
    }
    __syncthreads();
    for (int idx = tid; idx < C_*T_; idx += 256) {
        int Co = idx >> 3, t = idx & 7;
        float aw = 0.f, ab = 0.f;
        const float* w1b = b_w  + (size_t)Co * CR_ * 3;
        const float* w2b = bb_w + (size_t)Co * CR_ * 3;
        for (int r = 0; r < CR_; r++) {
            float x0 = (t > 0) ? s_x1[r][t-1] : 0.f, x1 = s_x1[r][t], x2 = (t < 7) ? s_x1[r][t+1] : 0.f;
            const float* w1 = w1b + r*3;
            const float* w2 = w2b + r*3;
            aw += w1[0]*x0 + w1[1]*x1 + w1[2]*x2;
            ab += w2[0]*x0 + w2[1]*x1 + w2[2]*x2;
        }
        g_walpha[b*C_*T_ + idx] = aw;
        g_balpha[b*C_*T_ + idx] = ab;
    }
}

// ---- weight prepack: g_wp[((tap*8+kc)*256 + o)*32 + cc] = tf32(W[o][kc*32+cc][ky][kx]) ----
__global__ void prepack_w_kernel(const float* __restrict__ Wt) {
    int idx = blockIdx.x * 256 + threadIdx.x;   // < 589824
    int cc = idx & 31, o = (idx >> 5) & 255, kc = (idx >> 13) & 7, tap = idx >> 16;
    int ky = tap / 3, kx = tap % 3;
    g_wp[idx] = totf32(Wt[(((size_t)o*C_ + kc*32 + cc)*3 + ky)*3 + kx]);
}

// ---- stage scaled input -> padded NHWC tf32: g_xs[(img*PXI + r*64 + x)*256 + c] ----
__global__ void stage_xs_kernel(const float* __restrict__ feat) {
    __shared__ float s[32][65];
    int img = blockIdx.z, r = blockIdx.y, c0 = blockIdx.x * 32;
    int b = img >> 3, t = img & 7;
    int tid = threadIdx.x;
    int x = tid & 63, cl0 = tid >> 6;
    for (int cl = cl0; cl < 32; cl += 4) {
        float v = 0.f;
        if (r >= 1 && r <= 56 && x >= 1 && x <= 56) {
            int c = c0 + cl;
            v = feat[(((size_t)(b*C_ + c))*T_ + t)*HW_ + (r-1)*W_ + (x-1)] * g_walpha[(b*C_ + c)*T_ + t];
        }
        s[cl][x] = totf32(v);
    }
    __syncthreads();
    int k = tid & 31, x0 = tid >> 5;
    for (int xx = x0; xx < 64; xx += 8)
        g_xs[((size_t)img*PXI_ + r*PC_ + xx)*C_ + c0 + k] = s[k][xx];
}

// ---------------- conv: implicit GEMM via mma.sync tf32 ----------------
// grid (28 ytiles, 64 imgs), 256 threads. Block: M=128 (2 out rows), N=256, K=9*256.
#define SMEM_FLOATS (256 + 258*AST + 2*256*AST)
__global__ void __launch_bounds__(256, 1)
conv_mma_kernel(const float* __restrict__ bias_p)
{
    extern __shared__ float sm[];
    float* bias_sm = sm;                 // 256
    float* As = sm + 256;                // 258*36
    float* Bs = As + 258*AST;            // 2 * 256*36
    uint32_t as_u = smem_to_u32(As);
    uint32_t bs_u = smem_to_u32(Bs);

    int tid = threadIdx.x, lane = tid & 31, wid = tid >> 5;
    int wm = wid >> 2, wn = wid & 3;     // warp 2x4 (M x N)
    int mg = lane >> 2, tg = lane & 3;
    int img = blockIdx.y, yt = blockIdx.x;
    int b = img >> 3, t = img & 7;
    size_t imgP = (size_t)img * PXI_ + (size_t)yt * 128;   // base pixel (2 padded rows)

    if (tid < 256)
        bias_sm[tid] = g_balpha[(b*C_ + tid)*T_ + t] * bias_p[tid];

    float acc[4][8][4] = {};

    for (int kc = 0; kc < 8; kc++) {
        // stage A: 258 pixel-rows x 32 ch (covers all tap shifts: off in [0,130])
        const float* srcA = g_xs + imgP*C_ + kc*32;
        for (int idx = tid; idx < 258*8; idx += 256) {
            int p = idx >> 3, kq = idx & 7;
            cp_async16(as_u + (uint32_t)(p*AST + kq*4)*4, srcA + (size_t)p*C_ + kq*4);
        }
        // stage B tap0 -> buf0
        {
            const float* srcB = g_wp + (size_t)kc*8192;
            for (int idx = tid; idx < 2048; idx += 256)
                cp_async16(bs_u + (uint32_t)((idx>>3)*AST + (idx&7)*4)*4, srcB + idx*4);
        }
        CP_COMMIT(); CP_WAIT_ALL();
        __syncthreads();

        for (int tap = 0; tap < 9; tap++) {
            int buf = tap & 1;
            if (tap < 8) {      // prefetch next B into other buffer
                const float* srcB = g_wp + (size_t)((tap+1)*8 + kc)*8192;
                uint32_t dstb = bs_u + (uint32_t)((buf^1)*256*AST)*4;
                for (int idx = tid; idx < 2048; idx += 256)
                    cp_async16(dstb + (uint32_t)((idx>>3)*AST + (idx&7)*4)*4, srcB + idx*4);
                CP_COMMIT();
            }
            int off = (tap/3)*64 + (tap%3);          // A row shift for this tap
            const float* Bbuf = Bs + buf*256*AST;
            #pragma unroll
            for (int ks = 0; ks < 4; ks++) {
                int k0 = ks*8;
                uint32_t af[4][4];
                #pragma unroll
                for (int i = 0; i < 4; i++) {
                    int rb = off + wm*64 + i*16 + mg;
                    af[i][0] = __float_as_uint(As[rb*AST + k0 + tg]);
                    af[i][1] = __float_as_uint(As[(rb+8)*AST + k0 + tg]);
                    af[i][2] = __float_as_uint(As[rb*AST + k0 + tg + 4]);
                    af[i][3] = __float_as_uint(As[(rb+8)*AST + k0 + tg + 4]);
                }
                #pragma unroll
                for (int j = 0; j < 8; j++) {
                    int nb = wn*64 + j*8 + mg;
                    uint32_t b0 = __float_as_uint(Bbuf[nb*AST + k0 + tg]);
                    uint32_t b1 = __float_as_uint(Bbuf[nb*AST + k0 + tg + 4]);
                    #pragma unroll
                    for (int i = 0; i < 4; i++)
                        mma_tf32(acc[i][j], af[i], b0, b1);
                }
            }
            if (tap < 8) CP_WAIT0();
            __syncthreads();
        }
    }

    // epilogue: acc -> g_conv (NCTHW) + bias; 32B-contiguous store segments
    #pragma unroll
    for (int i = 0; i < 4; i++) {
        #pragma unroll
        for (int j = 0; j < 8; j++) {
            #pragma unroll
            for (int e = 0; e < 4; e++) {
                int m = wm*64 + i*16 + mg + (e>>1)*8;
                int n = wn*64 + j*8 + tg*2 + (e&1);
                int x = m & 63;
                if (x < 56) {
                    int y = yt*2 + (m>>6);
                    g_conv[(((size_t)(b*C_ + n))*T_ + t)*HW_ + y*W_ + x] = acc[i][j][e] + bias_sm[n];
                }
            }
        }
    }
}

// ---------------- stats + final ----------------
__global__ void zero_stats_kernel() {
    int i = threadIdx.x + blockIdx.x * blockDim.x;
    if (i < C_*4) ((double*)g_stats)[i] = 0.0;
}
__global__ void stats_kernel() {
    int c = blockIdx.y;
    int item = blockIdx.x * blockDim.x + threadIdx.x;
    int b = item / HW_, hw = item % HW_;
    size_t base = (((size_t)b*C_ + c)*T_) * HW_ + hw;
    float so = 0.f, sq = 0.f, sa = 0.f, sqa = 0.f, prev = 0.f, cur = g_conv[base];
    #pragma unroll
    for (int t = 0; t < T_; t++) {
        float nxt = (t < T_-1) ? g_conv[base + (size_t)(t+1)*HW_] : 0.f;
        so += cur; sq += cur*cur;
        float ap = (prev + cur + nxt) * (1.f/3.f);
        sa += ap; sqa += ap*ap;
        prev = cur; cur = nxt;
    }
    __shared__ float sb[4][8];
    for (int o = 16; o; o >>= 1) {
        so += __shfl_down_sync(0xffffffffu, so, o);
        sq += __shfl_down_sync(0xffffffffu, sq, o);
        sa += __shfl_down_sync(0xffffffffu, sa, o);
        sqa += __shfl_down_sync(0xffffffffu, sqa, o);
    }
    int lane = threadIdx.x & 31, w = threadIdx.x >> 5;
    if (lane == 0) { sb[0][w] = so; sb[1][w] = sq; sb[2][w] = sa; sb[3][w] = sqa; }
    __syncthreads();
    if (threadIdx.x == 0) {
        float a0=0, a1=0, a2=0, a3=0;
        for (int i = 0; i < 8; i++) { a0+=sb[0][i]; a1+=sb[1][i]; a2+=sb[2][i]; a3+=sb[3][i]; }
        atomicAdd(&g_stats[c][0], (double)a0);
        atomicAdd(&g_stats[c][1], (double)a1);
        atomicAdd(&g_stats[c][2], (double)a2);
        atomicAdd(&g_stats[c][3], (double)a3);
    }
}
__global__ void final_kernel(const float* __restrict__ gamma_a, const float* __restrict__ beta_a,
                             const float* __restrict__ gamma_b, const float* __restrict__ beta_b,
                             float* __restrict__ out)
{
    int c = blockIdx.y;
    int item = blockIdx.x * blockDim.x + threadIdx.x;
    int b = item / HW_, hw = item % HW_;
    const double N = (double)B_ * T_ * HW_;
    double mu_a = g_stats[c][0] / N, va = g_stats[c][1] / N - mu_a*mu_a;
    double mu_b = g_stats[c][2] / N, vb = g_stats[c][3] / N - mu_b*mu_b;
    float sca = gamma_a[c] * (float)(1.0 / sqrt(va + 1e-5));
    float sha = beta_a[c] - (float)mu_a * sca;
    float scb = gamma_b[c] * (float)(1.0 / sqrt(vb + 1e-5));
    float shb = beta_b[c] - (float)mu_b * scb;
    size_t base = (((size_t)b*C_ + c)*T_) * HW_ + hw;
    float prev = 0.f, cur = g_conv[base];
    #pragma unroll
    for (int t = 0; t < T_; t++) {
        float nxt = (t < T_-1) ? g_conv[base + (size_t)(t+1)*HW_] : 0.f;
        float ap = (prev + cur + nxt) * (1.f/3.f);
        out[base + (size_t)t*HW_] = cur*sca + sha + ap*scb + shb;
        prev = cur; cur = nxt;
    }
}

// ---------------------------------------------------------------------------
extern "C" void kernel_launch(void* const* d_in, const int* in_sizes, int n_in,
                              void* d_out, int out_size)
{
    const float* feat    = (const float*)d_in[0];
    const float* Wt      = (const float*)d_in[1];
    const float* bias_p  = (const float*)d_in[2];
    const float* a_w     = (const float*)d_in[3];
    const float* a_b     = (const float*)d_in[4];
    const float* norm_w  = (const float*)d_in[5];
    const float* norm_b  = (const float*)d_in[6];
    const float* normt_w = (const float*)d_in[7];
    const float* normt_b = (const float*)d_in[8];
    const float* qkv_w   = (const float*)d_in[9];
    const float* qkv_b   = (const float*)d_in[10];
    const float* ao_w    = (const float*)d_in[11];
    const float* ao_b    = (const float*)d_in[12];
    const float* b_w     = (const float*)d_in[13];
    const float* bb_w    = (const float*)d_in[14];
    const float* gamma_a = (const float*)d_in[15];
    const float* beta_a  = (const float*)d_in[16];
    const float* gamma_b = (const float*)d_in[17];
    const float* beta_b  = (const float*)d_in[18];
    float* out = (float*)d_out;

    static int smem_set = 0;
    if (!smem_set) {
        cudaFuncSetAttribute(conv_mma_kernel, cudaFuncAttributeMaxDynamicSharedMemorySize,
                             SMEM_FLOATS * 4);
        smem_set = 1;
    }

    pool_kernel<<<B_*C_*T_, 128>>>(feat);
    routing_kernel<<<B_, 256>>>(a_w, a_b, norm_w, norm_b, normt_w, normt_b,
                                qkv_w, qkv_b, ao_w, ao_b, b_w, bb_w);
    prepack_w_kernel<<<2304, 256>>>(Wt);
    stage_xs_kernel<<<dim3(8, PR_, NIMG), 256>>>(feat);
    conv_mma_kernel<<<dim3(28, NIMG), 256, SMEM_FLOATS * 4>>>(bias_p);
    zero_stats_kernel<<<4, 256>>>();
    stats_kernel<<<dim3(98, 256), 256>>>();
    final_kernel<<<dim3(98, 256), 256>>>(gamma_a, beta_a, gamma_b, beta_b, out);
}